// round 14
// baseline (speedup 1.0000x reference)
#include <cuda_runtime.h>
#include <cstdint>

#define NB      32768
#define IN_DIM  2048
#define OUT_DIM 2432

#define C_INV3 0.57735026918962576451f
#define C_INV5 0.44721359549995793928f
#define C_INV7 0.37796447300922722721f

// Scratch for mode-1 mixed factors: [NB][384], pre-scaled by 1/sqrt(d).
__device__ float g_mixed[(size_t)NB * 384];
// Work-stealing counters (one per path). Zeroed by mode1_mma block 0 each run.
__device__ unsigned g_ctr[8];

// ---------------- tf32 mma.sync helpers (base sm_103) ----------------
__device__ __forceinline__ uint32_t cvt_tf32(float x) {
    uint32_t r; asm("cvt.rna.tf32.f32 %0, %1;" : "=r"(r) : "f"(x)); return r;
}
__device__ __forceinline__ void mma_tf32(float c[4], const uint32_t a[4],
                                         uint32_t b0, uint32_t b1) {
    asm volatile(
        "mma.sync.aligned.m16n8k8.row.col.f32.tf32.tf32.f32 "
        "{%0,%1,%2,%3}, {%4,%5,%6,%7}, {%8,%9}, {%0,%1,%2,%3};"
        : "+f"(c[0]), "+f"(c[1]), "+f"(c[2]), "+f"(c[3])
        : "r"(a[0]), "r"(a[1]), "r"(a[2]), "r"(a[3]), "r"(b0), "r"(b1));
}
__device__ __forceinline__ void bar_g(int id) {
    asm volatile("bar.sync %0, 128;" :: "r"(id) : "memory");
}

// ---------------------------------------------------------------------------
// mode-1 GEMM, N-split across CTA pairs for 2 CTAs/SM occupancy:
//   g_mixed[b, u'] = sum_v x2[b,v] * W'[u',v] * scale(u')
// CTA c owns n-half h=c&1 (u' in [h*192, h*192+192)) and tiles s = c>>1 + 148k.
// Also zeroes the work-stealing counters for tc_fused (block 0, kernel start).
// ---------------------------------------------------------------------------
__global__ void __launch_bounds__(256, 2)
mode1_mma(const float* __restrict__ x2, const float* __restrict__ weight)
{
    extern __shared__ float sm[];
    uint32_t* Wb  = (uint32_t*)sm;          // [192][128] swizzled (this half)
    float*    x2s = sm + 192 * 128;         // [16][132]
    uint32_t* x2u = (uint32_t*)x2s;

    const int tid  = threadIdx.x;
    const int lane = tid & 31;
    const int warp = tid >> 5;
    const int gid  = lane >> 2;
    const int tig  = lane & 3;
    const int h    = blockIdx.x & 1;        // n-half
    const int uoff = h * 192;

    if (blockIdx.x == 0 && tid < 8) g_ctr[tid] = 0;   // reset for tc_fused

    // Build this half of W' (scaled, tf32, swizzled). Once.
    for (int f = tid; f < 192 * 32; f += 256) {
        int lu = f >> 5, q = f & 31;
        int u  = uoff + lu;
        int p  = u >> 7;
        float sc = (p == 0) ? C_INV3 : ((p == 1) ? C_INV5 : C_INV7);
        float4 w4 = ((const float4*)(weight + 4 * 16384))[u * 32 + q];
        float c[4] = {w4.x * sc, w4.y * sc, w4.z * sc, w4.w * sc};
        int sw = (lu & 7) << 2;
        #pragma unroll
        for (int j = 0; j < 4; j++)
            Wb[lu * 128 + ((4 * q + j) ^ sw)] = cvt_tf32(c[j]);
    }
    __syncthreads();

    const int n_base = warp * 24;           // 8 warps x 24 local cols = 192
    const int t0 = tid >> 5, t1 = t0 + 8;
    const int q0 = tid & 31;

    float4 pre[2];
    auto load_tile = [&](int b0) {
        pre[0] = __ldg((const float4*)(x2 + (size_t)(b0 + t0) * IN_DIM) + q0);
        pre[1] = __ldg((const float4*)(x2 + (size_t)(b0 + t1) * IN_DIM) + q0);
    };

    int s = blockIdx.x >> 1;
    const int sstep = gridDim.x >> 1;
    if (s < NB / 16) load_tile(s * 16);

    for (; s < NB / 16; s += sstep) {
        const int b0 = s * 16;
        {
            uint4 o0, o1;
            o0.x = cvt_tf32(pre[0].x); o0.y = cvt_tf32(pre[0].y);
            o0.z = cvt_tf32(pre[0].z); o0.w = cvt_tf32(pre[0].w);
            o1.x = cvt_tf32(pre[1].x); o1.y = cvt_tf32(pre[1].y);
            o1.z = cvt_tf32(pre[1].z); o1.w = cvt_tf32(pre[1].w);
            *(uint4*)(x2u + t0 * 132 + 4 * q0) = o0;
            *(uint4*)(x2u + t1 * 132 + 4 * q0) = o1;
        }
        __syncthreads();

        float acc[3][4];
        #pragma unroll
        for (int nt = 0; nt < 3; nt++)
            #pragma unroll
            for (int j = 0; j < 4; j++) acc[nt][j] = 0.0f;

        #pragma unroll
        for (int s16 = 0; s16 < 16; s16++) {
            const int v0 = 8 * s16;
            uint32_t a[4];
            a[0] = x2u[(gid    ) * 132 + v0 + tig    ];
            a[1] = x2u[(gid + 8) * 132 + v0 + tig    ];
            a[2] = x2u[(gid    ) * 132 + v0 + tig + 4];
            a[3] = x2u[(gid + 8) * 132 + v0 + tig + 4];
            #pragma unroll
            for (int nt = 0; nt < 3; nt++) {
                int ur = n_base + nt * 8 + gid;        // local W' row
                int sw = (ur & 7) << 2;
                uint32_t b0r = Wb[ur * 128 + ((v0 + tig    ) ^ sw)];
                uint32_t b1r = Wb[ur * 128 + ((v0 + tig + 4) ^ sw)];
                mma_tf32(acc[nt], a, b0r, b1r);
            }
        }

        if (s + sstep < NB / 16) load_tile((s + sstep) * 16);

        // Dump: c0,c1 -> row b0+gid; c2,c3 -> row b0+gid+8 (global col uoff+).
        #pragma unroll
        for (int nt = 0; nt < 3; nt++) {
            int n0 = uoff + n_base + nt * 8 + 2 * tig;
            float2 lo; lo.x = acc[nt][0]; lo.y = acc[nt][1];
            float2 hi; hi.x = acc[nt][2]; hi.y = acc[nt][3];
            *(float2*)(g_mixed + (size_t)(b0 + gid    ) * 384 + n0) = lo;
            *(float2*)(g_mixed + (size_t)(b0 + gid + 8) * 384 + n0) = hi;
        }
        __syncthreads();
    }
}

// ---------------------------------------------------------------------------
// run_path: one depth-D path with batch-tile T (rows per iteration).
// Inner loops verbatim from the 285us build (pitch-132, aliased B/Ts buffer,
// register prefetch NPRE); tiles claimed via g_ctr[kid].
//   GEMM per tile: M=128(u) x K=128(v) x N=T*D (n = t*D+k)
// ---------------------------------------------------------------------------
template<int D, int T, bool HAS_M1, int NPRE, int KID>
__device__ __forceinline__ void run_path(
    float* sm, volatile unsigned* slots,
    const float* __restrict__ x1, const float* __restrict__ x2,
    const float* __restrict__ weight, const float* __restrict__ mask,
    float* __restrict__ out,
    int in1s, int in2s, int outs0, int outs1, int ws0, int moff,
    float inv_d)
{
    constexpr int PW    = 132;
    constexpr int NT    = NB / T;        // tiles total
    constexpr int NTile = T * D / 8;     // n8-tiles per tile
    constexpr int BI    = T * D / 4;     // build float4 chunks per thread
    constexpr int BW    = T * D * PW;    // buffer words per group

    uint32_t* Wu = (uint32_t*)sm;                       // [128][PW]
    const int tid  = threadIdx.x;
    const int g    = tid >> 7;
    const int gt   = tid & 127;
    const int lane = tid & 31;
    const int wg   = (tid >> 5) & 3;
    const int gid  = lane >> 2;
    const int tig  = lane & 3;
    const int bar  = g + 1;

    float*    BT  = sm + 128 * PW + g * BW;             // aliased B/Ts buffer
    uint32_t* BTu = (uint32_t*)BT;

    // Claim first tile before deciding whether to build W at all.
    if (gt == 0) slots[g] = atomicAdd(&g_ctr[KID], 1);
    __syncthreads();
    if (slots[0] >= NT && slots[1] >= NT && slots[2] >= NT && slots[3] >= NT)
        return;                                         // path already done

    // Build Ws (tf32, pitch 132). All 512 threads.
    for (int f = tid; f < 128 * 32; f += 512) {
        int u = f >> 5, q = f & 31;
        float4 w4 = ((const float4*)(weight + ws0))[f];
        uint4 o;
        o.x = cvt_tf32(w4.x); o.y = cvt_tf32(w4.y);
        o.z = cvt_tf32(w4.z); o.w = cvt_tf32(w4.w);
        *(uint4*)(Wu + u * PW + 4 * q) = o;
    }
    __syncthreads();

    float4 pre[NPRE > 0 ? NPRE : 1];
    auto load_tile = [&](int b0) {
        #pragma unroll
        for (int i = 0; i < NPRE; i++) {
            int f = gt + 128 * i;
            int t = f / (32 * D);
            int q = f - t * (32 * D);
            pre[i] = __ldg((const float4*)(x2 + (size_t)(b0 + t) * IN_DIM + in2s) + q);
        }
    };

    int s = (int)slots[g];
    if (NPRE > 0 && s < NT) load_tile(s * T);

    while (s < NT) {
        const int b0 = s * T;

        // ---- build B: BT[t*D+k][v] = tf32(x2[b0+t, in2s + v*D + k]) ----
        #pragma unroll
        for (int i = 0; i < BI; i++) {
            int f = gt + 128 * i;
            int t = f / (32 * D);
            int q = f - t * (32 * D);
            float4 v4;
            if (i < NPRE) v4 = pre[i];
            else v4 = __ldg((const float4*)(x2 + (size_t)(b0 + t) * IN_DIM + in2s) + q);
            float c[4] = {v4.x, v4.y, v4.z, v4.w};
            int e = 4 * q;
            #pragma unroll
            for (int j = 0; j < 4; j++) {
                int v = (e + j) / D, k = (e + j) % D;
                BTu[(t * D + k) * PW + v] = cvt_tf32(c[j]);
            }
        }
        bar_g(bar);

        // ---- MMA: 16 K-steps of k=8 ----
        float acc[2][NTile][4];
        #pragma unroll
        for (int mt = 0; mt < 2; mt++)
            #pragma unroll
            for (int nt = 0; nt < NTile; nt++)
                #pragma unroll
                for (int j = 0; j < 4; j++) acc[mt][nt][j] = 0.0f;

        #pragma unroll
        for (int s16 = 0; s16 < 16; s16++) {
            const int v0 = 8 * s16;
            uint32_t a[2][4];
            #pragma unroll
            for (int mt = 0; mt < 2; mt++) {
                int u0 = wg * 32 + mt * 16;
                a[mt][0] = Wu[(u0 + gid    ) * PW + v0 + tig    ];
                a[mt][1] = Wu[(u0 + gid + 8) * PW + v0 + tig    ];
                a[mt][2] = Wu[(u0 + gid    ) * PW + v0 + tig + 4];
                a[mt][3] = Wu[(u0 + gid + 8) * PW + v0 + tig + 4];
            }
            #pragma unroll
            for (int nt = 0; nt < NTile; nt++) {
                uint32_t b0r = BTu[(nt * 8 + gid) * PW + v0 + tig    ];
                uint32_t b1r = BTu[(nt * 8 + gid) * PW + v0 + tig + 4];
                mma_tf32(acc[0][nt], a[0], b0r, b1r);
                mma_tf32(acc[1][nt], a[1], b0r, b1r);
            }
        }
        if (gt == 0) slots[g] = atomicAdd(&g_ctr[KID], 1);   // claim next
        bar_g(bar);          // B consumed; slot visible to group

        int snext = (int)slots[g];
        if (NPRE > 0 && snext < NT) load_tile(snext * T);

        // ---- dump accums into the same buffer as Ts[n][u] ----
        #pragma unroll
        for (int mt = 0; mt < 2; mt++) {
            int ub = wg * 32 + mt * 16 + gid;
            #pragma unroll
            for (int nt = 0; nt < NTile; nt++) {
                int n0 = nt * 8 + 2 * tig;
                BT[(n0    ) * PW + ub    ] = acc[mt][nt][0];
                BT[(n0 + 1) * PW + ub    ] = acc[mt][nt][1];
                BT[(n0    ) * PW + ub + 8] = acc[mt][nt][2];
                BT[(n0 + 1) * PW + ub + 8] = acc[mt][nt][3];
            }
        }
        bar_g(bar);

        // ---- vectorized epilogue: warp wg handles t = p*4+wg, lane owns 4u ----
        #pragma unroll
        for (int p = 0; p < T / 4; p++) {
            const int t = p * 4 + wg;
            const size_t b = (size_t)(b0 + t);

            float xv[4 * D];
            float tv[4 * D];
            const float4* x1p =
                (const float4*)(x1 + b * IN_DIM + in1s + (size_t)4 * lane * D);
            #pragma unroll
            for (int q = 0; q < D; q++) {
                float4 t4 = __ldg(x1p + q);
                xv[4 * q + 0] = t4.x; xv[4 * q + 1] = t4.y;
                xv[4 * q + 2] = t4.z; xv[4 * q + 3] = t4.w;
            }
            #pragma unroll
            for (int k = 0; k < D; k++) {
                float4 t4 = *(const float4*)(BT + (t * D + k) * PW + 4 * lane);
                tv[4 * k + 0] = t4.x; tv[4 * k + 1] = t4.y;
                tv[4 * k + 2] = t4.z; tv[4 * k + 3] = t4.w;
            }

            float m4[4] = {0.0f, 0.0f, 0.0f, 0.0f};
            #pragma unroll
            for (int uj = 0; uj < 4; uj++)
                #pragma unroll
                for (int k = 0; k < D; k++)
                    m4[uj] = fmaf(xv[uj * D + k], tv[4 * k + uj], m4[uj]);

            {
                float4 mk = __ldg((const float4*)(mask + outs0) + lane);
                float4 o;
                o.x = m4[0] * inv_d * mk.x; o.y = m4[1] * inv_d * mk.y;
                o.z = m4[2] * inv_d * mk.z; o.w = m4[3] * inv_d * mk.w;
                *(float4*)(out + b * OUT_DIM + outs0 + 4 * lane) = o;
            }

            if (HAS_M1) {
                float4 mx = __ldg((const float4*)(g_mixed + b * 384 + moff) + lane);
                float mix[4] = {mx.x, mx.y, mx.z, mx.w};
                const float4* mk1 =
                    (const float4*)(mask + outs1 + (size_t)4 * lane * D);
                float4* op = (float4*)(out + b * OUT_DIM + outs1 +
                                       (size_t)4 * lane * D);
                #pragma unroll
                for (int q = 0; q < D; q++) {
                    float4 mq = __ldg(mk1 + q);
                    float4 o;
                    o.x = xv[4 * q + 0] * mix[(4 * q + 0) / D] * mq.x;
                    o.y = xv[4 * q + 1] * mix[(4 * q + 1) / D] * mq.y;
                    o.z = xv[4 * q + 2] * mix[(4 * q + 2) / D] * mq.z;
                    o.w = xv[4 * q + 3] * mix[(4 * q + 3) / D] * mq.w;
                    op[q] = o;
                }
            }
        }
        bar_g(bar);          // Ts reads done before next build overwrites
        s = snext;
    }
}

// ---------------------------------------------------------------------------
// Fused tc kernel: each CTA starts on a path sized to its work share, then
// migrates to the next unfinished path (counters guarantee exactly-once).
// Path index: 0=D1(T32), 1=D3(T16), 2=D5(T8), 3=D7(T8).
// ---------------------------------------------------------------------------
__global__ void __launch_bounds__(512, 1)
tc_fused(const float* __restrict__ x1, const float* __restrict__ x2,
         const float* __restrict__ weight, const float* __restrict__ mask,
         float* __restrict__ out)
{
    extern __shared__ float sm[];
    // slots live past the largest path buffer: 128*132 + 4*8*7*132 words
    volatile unsigned* slots =
        (volatile unsigned*)(sm + 128 * 132 + 4 * 8 * 7 * 132);

    // Initial path by work share (D7:55, D5:43, D3:31, D1:19 of 148).
    const int b = blockIdx.x;
    int start;
    if      (b < 55)  start = 3;
    else if (b < 98)  start = 2;
    else if (b < 129) start = 1;
    else              start = 0;

    #pragma unroll
    for (int pass = 0; pass < 4; pass++) {
        int p = (start + pass) & 3;
        __syncthreads();   // previous pass fully done (W/BT reuse safe)
        switch (p) {
        case 0:
            run_path<1, 32, false, 8, 0>(sm, slots, x1, x2, weight, mask, out,
                                         0, 0, 0, 0, 0 * 16384, 0, 1.0f);
            break;
        case 1:
            run_path<3, 16, true, 6, 1>(sm, slots, x1, x2, weight, mask, out,
                                        128, 128, 128, 512, 1 * 16384, 0, C_INV3);
            break;
        case 2:
            run_path<5, 8, true, 10, 2>(sm, slots, x1, x2, weight, mask, out,
                                        512, 512, 256, 896, 2 * 16384, 128, C_INV5);
            break;
        case 3:
            run_path<7, 8, true, 7, 3>(sm, slots, x1, x2, weight, mask, out,
                                       1152, 1152, 384, 1536, 3 * 16384, 256, C_INV7);
            break;
        }
    }
}

// ---------------------------------------------------------------------------
extern "C" void kernel_launch(void* const* d_in, const int* in_sizes, int n_in,
                              void* d_out, int out_size)
{
    (void)in_sizes; (void)n_in; (void)out_size;
    const float* x1   = (const float*)d_in[0];
    const float* x2   = (const float*)d_in[1];
    const float* w    = (const float*)d_in[2];
    const float* mask = (const float*)d_in[3];
    float* out        = (float*)d_out;

    const int SM_M1 = (192 * 128 + 16 * 132) * 4;                 // 106752 (2/SM)
    const int SM_TF = (128 * 132 + 4 * 8 * 7 * 132 + 4) * 4;      // 185872

    cudaFuncSetAttribute(mode1_mma,
                         cudaFuncAttributeMaxDynamicSharedMemorySize, SM_M1);
    cudaFuncSetAttribute(tc_fused,
                         cudaFuncAttributeMaxDynamicSharedMemorySize, SM_TF);

    // mode1 first (zeroes g_ctr; tc_fused paths 3/5/7 consume g_mixed).
    mode1_mma<<<296, 256, SM_M1>>>(x2, w);
    tc_fused<<<148, 512, SM_TF>>>(x1, x2, w, mask, out);
}

// round 15
// speedup vs baseline: 1.2069x; 1.2069x over previous
#include <cuda_runtime.h>
#include <cuda_fp16.h>
#include <cstdint>

#define NB      32768
#define IN_DIM  2048
#define OUT_DIM 2432

#define C_INV3 0.57735026918962576451f
#define C_INV5 0.44721359549995793928f
#define C_INV7 0.37796447300922722721f

// Scratch for mode-1 mixed factors: [NB][384], pre-scaled by 1/sqrt(d).
__device__ float g_mixed[(size_t)NB * 384];
// Work-stealing counters (one per path). Zeroed by mode1_mma block 0 each run.
__device__ unsigned g_ctr[8];

// ---------------- fp16 mma.sync helpers (base sm_103) ----------------
__device__ __forceinline__ uint32_t pack_h2(float lo, float hi) {
    __half2 h = __floats2half2_rn(lo, hi);     // .x = lo half
    return *(uint32_t*)&h;
}
__device__ __forceinline__ void mma_f16(float c[4], const uint32_t a[4],
                                        uint32_t b0, uint32_t b1) {
    asm volatile(
        "mma.sync.aligned.m16n8k16.row.col.f32.f16.f16.f32 "
        "{%0,%1,%2,%3}, {%4,%5,%6,%7}, {%8,%9}, {%0,%1,%2,%3};"
        : "+f"(c[0]), "+f"(c[1]), "+f"(c[2]), "+f"(c[3])
        : "r"(a[0]), "r"(a[1]), "r"(a[2]), "r"(a[3]), "r"(b0), "r"(b1));
}
__device__ __forceinline__ void bar_g(int id) {
    asm volatile("bar.sync %0, 128;" :: "r"(id) : "memory");
}

#define PWA 68      // fp16x2-word pitch (136 halfs): bank = 4*gid+tig bijection
#define PWT 132     // fp32 pitch for Ts dump/epilogue (unchanged, proven)

// ---------------------------------------------------------------------------
// mode-1 GEMM (fp16 k16, N-split across CTA pairs, 2 CTAs/SM):
//   g_mixed[b, u'] = sum_v x2[b,v] * W'[u',v] * scale(u')
// Also zeroes the work-stealing counters for tc_fused (block 0).
// ---------------------------------------------------------------------------
__global__ void __launch_bounds__(256, 2)
mode1_mma(const float* __restrict__ x2, const float* __restrict__ weight)
{
    extern __shared__ float sm[];
    uint32_t* Wb  = (uint32_t*)sm;             // [192][PWA] fp16x2 words
    uint32_t* x2u = (uint32_t*)sm + 192 * PWA; // [16][PWA]

    const int tid  = threadIdx.x;
    const int lane = tid & 31;
    const int warp = tid >> 5;
    const int gid  = lane >> 2;
    const int tig  = lane & 3;
    const int h    = blockIdx.x & 1;           // n-half
    const int uoff = h * 192;

    if (blockIdx.x == 0 && tid < 8) g_ctr[tid] = 0;   // reset for tc_fused

    // Build this half of W' (scaled, fp16 pairs). Once.
    for (int f = tid; f < 192 * 32; f += 256) {
        int lu = f >> 5, q = f & 31;
        int u  = uoff + lu;
        int p  = u >> 7;
        float sc = (p == 0) ? C_INV3 : ((p == 1) ? C_INV5 : C_INV7);
        float4 w4 = ((const float4*)(weight + 4 * 16384))[u * 32 + q];
        uint2 o;
        o.x = pack_h2(w4.x * sc, w4.y * sc);
        o.y = pack_h2(w4.z * sc, w4.w * sc);
        *(uint2*)(Wb + lu * PWA + 2 * q) = o;
    }
    __syncthreads();

    const int n_base = warp * 24;              // 8 warps x 24 local cols = 192
    const int t0 = tid >> 5, t1 = t0 + 8;
    const int q0 = tid & 31;

    float4 pre[2];
    auto load_tile = [&](int b0) {
        pre[0] = __ldg((const float4*)(x2 + (size_t)(b0 + t0) * IN_DIM) + q0);
        pre[1] = __ldg((const float4*)(x2 + (size_t)(b0 + t1) * IN_DIM) + q0);
    };

    int s = blockIdx.x >> 1;
    const int sstep = gridDim.x >> 1;
    if (s < NB / 16) load_tile(s * 16);

    for (; s < NB / 16; s += sstep) {
        const int b0 = s * 16;
        {
            uint2 o0, o1;
            o0.x = pack_h2(pre[0].x, pre[0].y); o0.y = pack_h2(pre[0].z, pre[0].w);
            o1.x = pack_h2(pre[1].x, pre[1].y); o1.y = pack_h2(pre[1].z, pre[1].w);
            *(uint2*)(x2u + t0 * PWA + 2 * q0) = o0;
            *(uint2*)(x2u + t1 * PWA + 2 * q0) = o1;
        }
        __syncthreads();

        float acc[3][4];
        #pragma unroll
        for (int nt = 0; nt < 3; nt++)
            #pragma unroll
            for (int j = 0; j < 4; j++) acc[nt][j] = 0.0f;

        #pragma unroll
        for (int st = 0; st < 8; st++) {       // 8 K-steps of k16
            const int w0 = 8 * st;
            uint32_t a[4];
            a[0] = x2u[(gid    ) * PWA + w0 + tig    ];
            a[1] = x2u[(gid + 8) * PWA + w0 + tig    ];
            a[2] = x2u[(gid    ) * PWA + w0 + tig + 4];
            a[3] = x2u[(gid + 8) * PWA + w0 + tig + 4];
            #pragma unroll
            for (int nt = 0; nt < 3; nt++) {
                int ur = n_base + nt * 8 + gid;          // local W' row
                uint32_t b0r = Wb[ur * PWA + w0 + tig    ];
                uint32_t b1r = Wb[ur * PWA + w0 + tig + 4];
                mma_f16(acc[nt], a, b0r, b1r);
            }
        }

        if (s + sstep < NB / 16) load_tile((s + sstep) * 16);

        #pragma unroll
        for (int nt = 0; nt < 3; nt++) {
            int n0 = uoff + n_base + nt * 8 + 2 * tig;
            float2 lo; lo.x = acc[nt][0]; lo.y = acc[nt][1];
            float2 hi; hi.x = acc[nt][2]; hi.y = acc[nt][3];
            *(float2*)(g_mixed + (size_t)(b0 + gid    ) * 384 + n0) = lo;
            *(float2*)(g_mixed + (size_t)(b0 + gid + 8) * 384 + n0) = hi;
        }
        __syncthreads();
    }
}

// ---------------------------------------------------------------------------
// run_path: one depth-D path, batch-tile T; fp16 k16 fragments (pitch PWA),
// fp32 Ts dump/epilogue (pitch PWT) in the same aliased buffer.
//   GEMM per tile: M=128(u) x K=128(v) x N=T*D (n = t*D+k)
// ---------------------------------------------------------------------------
template<int D, int T, bool HAS_M1, int NPRE, int KID>
__device__ __forceinline__ void run_path(
    float* sm, volatile unsigned* slots,
    const float* __restrict__ x1, const float* __restrict__ x2,
    const float* __restrict__ weight, const float* __restrict__ mask,
    float* __restrict__ out,
    int in1s, int in2s, int outs0, int outs1, int ws0, int moff,
    float inv_d)
{
    constexpr int NT    = NB / T;        // tiles total
    constexpr int NTile = T * D / 8;     // n8-tiles per tile
    constexpr int BI    = T * D / 4;     // build float4 chunks per thread
    constexpr int BW    = T * D * PWT;   // buffer fp32-words per group (Ts)

    uint32_t* Wu = (uint32_t*)sm;                       // [128][PWA]
    const int tid  = threadIdx.x;
    const int g    = tid >> 7;
    const int gt   = tid & 127;
    const int lane = tid & 31;
    const int wg   = (tid >> 5) & 3;
    const int gid  = lane >> 2;
    const int tig  = lane & 3;
    const int bar  = g + 1;

    float*    BT  = sm + 128 * PWA + g * BW;            // aliased B/Ts buffer
    uint32_t* Bw  = (uint32_t*)BT;                      // B as fp16x2 words
    __half*   Bh  = (__half*)BT;                        // B as halfs (scatter)

    // Claim first tile before deciding whether to build W at all.
    if (gt == 0) slots[g] = atomicAdd(&g_ctr[KID], 1);
    __syncthreads();
    if (slots[0] >= NT && slots[1] >= NT && slots[2] >= NT && slots[3] >= NT)
        return;                                         // path already done

    // Build Ws (fp16 pairs, pitch PWA). All 512 threads.
    for (int f = tid; f < 128 * 32; f += 512) {
        int u = f >> 5, q = f & 31;
        float4 w4 = ((const float4*)(weight + ws0))[f];
        uint2 o;
        o.x = pack_h2(w4.x, w4.y);
        o.y = pack_h2(w4.z, w4.w);
        *(uint2*)(Wu + u * PWA + 2 * q) = o;
    }
    __syncthreads();

    float4 pre[NPRE > 0 ? NPRE : 1];
    auto load_tile = [&](int b0) {
        #pragma unroll
        for (int i = 0; i < NPRE; i++) {
            int f = gt + 128 * i;
            int t = f / (32 * D);
            int q = f - t * (32 * D);
            pre[i] = __ldg((const float4*)(x2 + (size_t)(b0 + t) * IN_DIM + in2s) + q);
        }
    };

    int s = (int)slots[g];
    if (NPRE > 0 && s < NT) load_tile(s * T);

    while (s < NT) {
        const int b0 = s * T;

        // ---- build B (fp16): row n = t*D+k, half-col v ----
        #pragma unroll
        for (int i = 0; i < BI; i++) {
            int f = gt + 128 * i;
            int t = f / (32 * D);
            int q = f - t * (32 * D);
            float4 v4;
            if (i < NPRE) v4 = pre[i];
            else v4 = __ldg((const float4*)(x2 + (size_t)(b0 + t) * IN_DIM + in2s) + q);
            if (D == 1) {
                uint2 o;
                o.x = pack_h2(v4.x, v4.y);
                o.y = pack_h2(v4.z, v4.w);
                *(uint2*)(Bw + t * PWA + 2 * q) = o;
            } else {
                float c[4] = {v4.x, v4.y, v4.z, v4.w};
                int e = 4 * q;
                #pragma unroll
                for (int j = 0; j < 4; j++) {
                    int v = (e + j) / D, k = (e + j) % D;
                    Bh[(t * D + k) * (2 * PWA) + v] = __float2half_rn(c[j]);
                }
            }
        }
        bar_g(bar);

        // ---- MMA: 8 K-steps of k16 ----
        float acc[2][NTile][4];
        #pragma unroll
        for (int mt = 0; mt < 2; mt++)
            #pragma unroll
            for (int nt = 0; nt < NTile; nt++)
                #pragma unroll
                for (int j = 0; j < 4; j++) acc[mt][nt][j] = 0.0f;

        #pragma unroll
        for (int st = 0; st < 8; st++) {
            const int w0 = 8 * st;
            uint32_t a[2][4];
            #pragma unroll
            for (int mt = 0; mt < 2; mt++) {
                int u0 = wg * 32 + mt * 16;
                a[mt][0] = Wu[(u0 + gid    ) * PWA + w0 + tig    ];
                a[mt][1] = Wu[(u0 + gid + 8) * PWA + w0 + tig    ];
                a[mt][2] = Wu[(u0 + gid    ) * PWA + w0 + tig + 4];
                a[mt][3] = Wu[(u0 + gid + 8) * PWA + w0 + tig + 4];
            }
            #pragma unroll
            for (int nt = 0; nt < NTile; nt++) {
                uint32_t b0r = Bw[(nt * 8 + gid) * PWA + w0 + tig    ];
                uint32_t b1r = Bw[(nt * 8 + gid) * PWA + w0 + tig + 4];
                mma_f16(acc[0][nt], a[0], b0r, b1r);
                mma_f16(acc[1][nt], a[1], b0r, b1r);
            }
        }
        if (gt == 0) slots[g] = atomicAdd(&g_ctr[KID], 1);   // claim next
        bar_g(bar);          // B consumed; slot visible to group

        int snext = (int)slots[g];
        if (NPRE > 0 && snext < NT) load_tile(snext * T);

        // ---- dump accums (fp32) into the same buffer as Ts[n][u] ----
        #pragma unroll
        for (int mt = 0; mt < 2; mt++) {
            int ub = wg * 32 + mt * 16 + gid;
            #pragma unroll
            for (int nt = 0; nt < NTile; nt++) {
                int n0 = nt * 8 + 2 * tig;
                BT[(n0    ) * PWT + ub    ] = acc[mt][nt][0];
                BT[(n0 + 1) * PWT + ub    ] = acc[mt][nt][1];
                BT[(n0    ) * PWT + ub + 8] = acc[mt][nt][2];
                BT[(n0 + 1) * PWT + ub + 8] = acc[mt][nt][3];
            }
        }
        bar_g(bar);

        // ---- vectorized epilogue: warp wg handles t = p*4+wg, lane owns 4u ----
        #pragma unroll
        for (int p = 0; p < T / 4; p++) {
            const int t = p * 4 + wg;
            const size_t b = (size_t)(b0 + t);

            float xv[4 * D];
            float tv[4 * D];
            const float4* x1p =
                (const float4*)(x1 + b * IN_DIM + in1s + (size_t)4 * lane * D);
            #pragma unroll
            for (int q = 0; q < D; q++) {
                float4 t4 = __ldg(x1p + q);
                xv[4 * q + 0] = t4.x; xv[4 * q + 1] = t4.y;
                xv[4 * q + 2] = t4.z; xv[4 * q + 3] = t4.w;
            }
            #pragma unroll
            for (int k = 0; k < D; k++) {
                float4 t4 = *(const float4*)(BT + (t * D + k) * PWT + 4 * lane);
                tv[4 * k + 0] = t4.x; tv[4 * k + 1] = t4.y;
                tv[4 * k + 2] = t4.z; tv[4 * k + 3] = t4.w;
            }

            float m4[4] = {0.0f, 0.0f, 0.0f, 0.0f};
            #pragma unroll
            for (int uj = 0; uj < 4; uj++)
                #pragma unroll
                for (int k = 0; k < D; k++)
                    m4[uj] = fmaf(xv[uj * D + k], tv[4 * k + uj], m4[uj]);

            {
                float4 mk = __ldg((const float4*)(mask + outs0) + lane);
                float4 o;
                o.x = m4[0] * inv_d * mk.x; o.y = m4[1] * inv_d * mk.y;
                o.z = m4[2] * inv_d * mk.z; o.w = m4[3] * inv_d * mk.w;
                *(float4*)(out + b * OUT_DIM + outs0 + 4 * lane) = o;
            }

            if (HAS_M1) {
                float4 mx = __ldg((const float4*)(g_mixed + b * 384 + moff) + lane);
                float mix[4] = {mx.x, mx.y, mx.z, mx.w};
                const float4* mk1 =
                    (const float4*)(mask + outs1 + (size_t)4 * lane * D);
                float4* op = (float4*)(out + b * OUT_DIM + outs1 +
                                       (size_t)4 * lane * D);
                #pragma unroll
                for (int q = 0; q < D; q++) {
                    float4 mq = __ldg(mk1 + q);
                    float4 o;
                    o.x = xv[4 * q + 0] * mix[(4 * q + 0) / D] * mq.x;
                    o.y = xv[4 * q + 1] * mix[(4 * q + 1) / D] * mq.y;
                    o.z = xv[4 * q + 2] * mix[(4 * q + 2) / D] * mq.z;
                    o.w = xv[4 * q + 3] * mix[(4 * q + 3) / D] * mq.w;
                    op[q] = o;
                }
            }
        }
        bar_g(bar);          // Ts reads done before next build overwrites
        s = snext;
    }
}

// ---------------------------------------------------------------------------
// Fused tc kernel: each CTA starts on a path sized to its work share, then
// migrates to the next unfinished path (counters guarantee exactly-once).
// Path index: 0=D1(T32), 1=D3(T16), 2=D5(T8), 3=D7(T8).
// ---------------------------------------------------------------------------
__global__ void __launch_bounds__(512, 1)
tc_fused(const float* __restrict__ x1, const float* __restrict__ x2,
         const float* __restrict__ weight, const float* __restrict__ mask,
         float* __restrict__ out)
{
    extern __shared__ float sm[];
    // slots live past the largest path buffer: 128*PWA + 4*56*PWT words
    volatile unsigned* slots =
        (volatile unsigned*)(sm + 128 * PWA + 4 * 56 * PWT);

    // Initial path by work share (D7:55, D5:43, D3:31, D1:19 of 148).
    const int b = blockIdx.x;
    int start;
    if      (b < 55)  start = 3;
    else if (b < 98)  start = 2;
    else if (b < 129) start = 1;
    else              start = 0;

    #pragma unroll
    for (int pass = 0; pass < 4; pass++) {
        int p = (start + pass) & 3;
        __syncthreads();   // previous pass fully done (W/BT reuse safe)
        switch (p) {
        case 0:
            run_path<1, 32, false, 8, 0>(sm, slots, x1, x2, weight, mask, out,
                                         0, 0, 0, 0, 0 * 16384, 0, 1.0f);
            break;
        case 1:
            run_path<3, 16, true, 6, 1>(sm, slots, x1, x2, weight, mask, out,
                                        128, 128, 128, 512, 1 * 16384, 0, C_INV3);
            break;
        case 2:
            run_path<5, 8, true, 10, 2>(sm, slots, x1, x2, weight, mask, out,
                                        512, 512, 256, 896, 2 * 16384, 128, C_INV5);
            break;
        case 3:
            run_path<7, 8, true, 7, 3>(sm, slots, x1, x2, weight, mask, out,
                                       1152, 1152, 384, 1536, 3 * 16384, 256, C_INV7);
            break;
        }
    }
}

// ---------------------------------------------------------------------------
extern "C" void kernel_launch(void* const* d_in, const int* in_sizes, int n_in,
                              void* d_out, int out_size)
{
    (void)in_sizes; (void)n_in; (void)out_size;
    const float* x1   = (const float*)d_in[0];
    const float* x2   = (const float*)d_in[1];
    const float* w    = (const float*)d_in[2];
    const float* mask = (const float*)d_in[3];
    float* out        = (float*)d_out;

    const int SM_M1 = (192 * PWA + 16 * PWA) * 4;                 //  56576 (2/SM)
    const int SM_TF = (128 * PWA + 4 * 56 * PWT + 4) * 4;         // 153104

    cudaFuncSetAttribute(mode1_mma,
                         cudaFuncAttributeMaxDynamicSharedMemorySize, SM_M1);
    cudaFuncSetAttribute(tc_fused,
                         cudaFuncAttributeMaxDynamicSharedMemorySize, SM_TF);

    // mode1 first (zeroes g_ctr; tc_fused paths 3/5/7 consume g_mixed).
    mode1_mma<<<296, 256, SM_M1>>>(x2, w);
    tc_fused<<<148, 512, SM_TF>>>(x1, x2, w, mask, out);
}